// round 6
// baseline (speedup 1.0000x reference)
#include <cuda_runtime.h>
#include <cuda_bf16.h>

// DigitCaps fused single-kernel for GB300 (sm_103a), round 4.
//
//   output[b,c] = (sum_n u[b,n,:]) . dc_new[c,:] / N
//   dc_new      = dc + (seg_u - counts*dc) / (B*N)
// One streaming pass computes sum_u[128][8], seg_u[10][8], counts[10] in global
// scratch; the LAST block (atomic counter) finalizes outputs and re-zeroes the
// scratch for the next graph replay.

#define Bsz    128
#define Jtot   4608
#define Cc     10
#define Dd     8
#define Mm     4
#define Ntot   (Jtot * Mm)          // 18432

#define JB     32
#define BB     32
#define NTHR   256
#define WSTR   260                  // padded W row stride (floats); 1040B = 16B-aligned
#define XSTR   258                  // padded X row stride (floats)
#define NPAIR  45                   // 40 seg bf16x2 pairs + 5 count pairs
#define NBLK   ((Jtot / JB) * (Bsz / BB))   // 576

// scratch: [0,1024) sum_u[b][d]; [1024,1104) seg[c*8+d]; [1104,1114) cnt[c]
__device__ float    g_scratch[1120];
__device__ unsigned g_done;

// ---- packed f32x2 helpers ----
__device__ __forceinline__ unsigned long long pk2(float lo, float hi) {
    unsigned long long r;
    asm("mov.b64 %0, {%1, %2};" : "=l"(r) : "f"(lo), "f"(hi));
    return r;
}
__device__ __forceinline__ float2 upk2(unsigned long long a) {
    float2 r;
    asm("mov.b64 {%0, %1}, %2;" : "=f"(r.x), "=f"(r.y) : "l"(a));
    return r;
}
__device__ __forceinline__ unsigned long long fma2(unsigned long long a,
                                                   unsigned long long b,
                                                   unsigned long long c) {
    unsigned long long d;
    asm("fma.rn.f32x2 %0, %1, %2, %3;" : "=l"(d) : "l"(a), "l"(b), "l"(c));
    return d;
}
__device__ __forceinline__ unsigned long long add2(unsigned long long a,
                                                   unsigned long long b) {
    unsigned long long d;
    asm("add.rn.f32x2 %0, %1, %2;" : "=l"(d) : "l"(a), "l"(b));
    return d;
}
// (lo,hi) f32 pair -> bf16x2 (lo in bits[15:0])
__device__ __forceinline__ unsigned cvt_bf16x2(unsigned long long p) {
    float2 t = upk2(p);
    unsigned r;
    asm("cvt.rn.bf16x2.f32 %0, %1, %2;" : "=r"(r) : "f"(t.y), "f"(t.x));
    return r;
}
__device__ __forceinline__ __nv_bfloat162 as_bf2(unsigned v) {
    return *(__nv_bfloat162*)&v;
}

extern __shared__ float smem[];

__global__ __launch_bounds__(NTHR, 2)
void caps_main_kernel(const float* __restrict__ xin,   // [B, J, 8]
                      const float* __restrict__ Wg,    // [J, 8, 32]
                      const float* __restrict__ dcg,   // [10, 8]
                      float* __restrict__ out)         // [128*10 + 80]
{
    float*    sW   = smem;                               // JB*WSTR = 8320 f
    float*    sX   = sW + JB * WSTR;                     // BB*XSTR = 8256 f
    unsigned* sSeg = (unsigned*)(sX + BB * XSTR);        // NPAIR*256 u32

    const int tid = threadIdx.x;
    const int j0  = blockIdx.x * JB;
    const int b0  = blockIdx.y * BB;

    // ---- stage W tile (padded rows, float4) ----
    {
        const float4* src = (const float4*)(Wg + (size_t)j0 * 256);
        #pragma unroll 4
        for (int i = tid; i < JB * 64; i += NTHR) {
            int jl = i >> 6, r = i & 63;
            ((float4*)(sW + jl * WSTR))[r] = src[i];
        }
    }
    // ---- stage X tile (padded rows, float2) ----
    {
        for (int i = tid; i < BB * 128; i += NTHR) {
            int bl = i >> 7, r = i & 127;
            const float2* src =
                (const float2*)(xin + (size_t)(b0 + bl) * (Jtot * 8) + (size_t)j0 * 8);
            ((float2*)(sX + bl * XSTR))[r] = src[r];
        }
    }
    // ---- zero private seg columns ----
    for (int i = tid; i < NPAIR * 256; i += NTHR) sSeg[i] = 0u;

    // ---- digit_caps as 40 bf16x2 (d-pair) registers ----
    __nv_bfloat162 rdc[Cc * 4];
    #pragma unroll
    for (int i = 0; i < Cc * 4; i++) {
        float2 v = ((const float2*)dcg)[i];
        rdc[i] = __float22bfloat162_rn(v);
    }

    __syncthreads();

    const int bl  = tid >> 3;
    const int sub = tid & 7;
    const int b   = b0 + bl;

    unsigned long long su0 = 0, su1 = 0, su2 = 0, su3 = 0;
    const float2* xrow = (const float2*)(sX + bl * XSTR);

    for (int it = 0; it < 16; ++it) {
        const int p  = it * 8 + sub;
        const int jl = p >> 2;
        const int m  = p & 3;

        const float2*     xs   = xrow + jl * 4;
        const ulonglong2* wrow = (const ulonglong2*)(sW + jl * WSTR);

        unsigned long long u0 = 0, u1 = 0, u2 = 0, u3 = 0;
        #pragma unroll
        for (int k = 0; k < 4; k++) {
            float2 xp = xs[k];
            unsigned long long xa = pk2(xp.x, xp.x);
            unsigned long long xb = pk2(xp.y, xp.y);
            // i = 2k: element index in ull2 units = i*8 + m*2
            ulonglong2 wA = wrow[(2 * k) * 8 + m * 2];
            ulonglong2 wB = wrow[(2 * k) * 8 + m * 2 + 1];
            u0 = fma2(xa, wA.x, u0);
            u1 = fma2(xa, wA.y, u1);
            u2 = fma2(xa, wB.x, u2);
            u3 = fma2(xa, wB.y, u3);
            ulonglong2 wC = wrow[(2 * k + 1) * 8 + m * 2];
            ulonglong2 wD = wrow[(2 * k + 1) * 8 + m * 2 + 1];
            u0 = fma2(xb, wC.x, u0);
            u1 = fma2(xb, wC.y, u1);
            u2 = fma2(xb, wD.x, u2);
            u3 = fma2(xb, wD.y, u3);
        }

        su0 = add2(su0, u0); su1 = add2(su1, u1);
        su2 = add2(su2, u2); su3 = add2(su3, u3);

        // bf16 votes (reused by sims AND seg accumulation)
        unsigned v0 = cvt_bf16x2(u0), v1 = cvt_bf16x2(u1);
        unsigned v2 = cvt_bf16x2(u2), v3 = cvt_bf16x2(u3);
        __nv_bfloat162 V0 = as_bf2(v0), V1 = as_bf2(v1);
        __nv_bfloat162 V2 = as_bf2(v2), V3 = as_bf2(v3);

        // argmax over classes via bf16x2 dot products (first-max semantics)
        float best;
        int   wbest = 0;
        #pragma unroll
        for (int c = 0; c < Cc; c++) {
            __nv_bfloat162 t0 = __hfma2(V1, rdc[c * 4 + 1], __hmul2(V0, rdc[c * 4]));
            __nv_bfloat162 t1 = __hfma2(V3, rdc[c * 4 + 3], __hmul2(V2, rdc[c * 4 + 2]));
            __nv_bfloat162 a  = __hadd2(t0, t1);
            unsigned ab = *(unsigned*)&a;
            float s = __uint_as_float(ab << 16) + __uint_as_float(ab & 0xFFFF0000u);
            if (c == 0) { best = s; }
            else if (s > best) { best = s; wbest = c; }
        }

        // per-thread-private bf16x2 segment accumulation (bank = tid%32)
        unsigned* segp = sSeg + wbest * 4 * 256 + tid;
        {
            unsigned o;
            __nv_bfloat162 r;
            o = segp[0];   r = __hadd2(as_bf2(o), V0); segp[0]   = *(unsigned*)&r;
            o = segp[256]; r = __hadd2(as_bf2(o), V1); segp[256] = *(unsigned*)&r;
            o = segp[512]; r = __hadd2(as_bf2(o), V2); segp[512] = *(unsigned*)&r;
            o = segp[768]; r = __hadd2(as_bf2(o), V3); segp[768] = *(unsigned*)&r;
            unsigned inc = (wbest & 1) ? 0x3F800000u : 0x00003F80u;
            unsigned* cp = sSeg + (40 + (wbest >> 1)) * 256 + tid;
            o = *cp;       r = __hadd2(as_bf2(o), as_bf2(inc)); *cp = *(unsigned*)&r;
        }
    }

    // ---- sum_u: reduce over the 8 threads sharing b ----
    #pragma unroll
    for (int d = 1; d < 8; d <<= 1) {
        su0 = add2(su0, __shfl_xor_sync(0xffffffffu, su0, d));
        su1 = add2(su1, __shfl_xor_sync(0xffffffffu, su1, d));
        su2 = add2(su2, __shfl_xor_sync(0xffffffffu, su2, d));
        su3 = add2(su3, __shfl_xor_sync(0xffffffffu, su3, d));
    }
    if (sub == 0) {
        float2 t;
        t = upk2(su0); atomicAdd(&g_scratch[b * 8 + 0], t.x); atomicAdd(&g_scratch[b * 8 + 1], t.y);
        t = upk2(su1); atomicAdd(&g_scratch[b * 8 + 2], t.x); atomicAdd(&g_scratch[b * 8 + 3], t.y);
        t = upk2(su2); atomicAdd(&g_scratch[b * 8 + 4], t.x); atomicAdd(&g_scratch[b * 8 + 5], t.y);
        t = upk2(su3); atomicAdd(&g_scratch[b * 8 + 6], t.x); atomicAdd(&g_scratch[b * 8 + 7], t.y);
    }

    __syncthreads();

    // ---- reduce the 45 private-pair slots; warp per slot, conflict-free ----
    const int warp = tid >> 5;
    const int lane = tid & 31;
    for (int slot = warp; slot < NPAIR; slot += 8) {
        const unsigned* base = sSeg + slot * 256;
        float sx = 0.0f, sy = 0.0f;
        #pragma unroll
        for (int k = 0; k < 8; k++) {
            unsigned v = base[k * 32 + lane];
            float2 f = __bfloat1622float2(as_bf2(v));
            sx += f.x; sy += f.y;
        }
        #pragma unroll
        for (int d = 16; d > 0; d >>= 1) {
            sx += __shfl_xor_sync(0xffffffffu, sx, d);
            sy += __shfl_xor_sync(0xffffffffu, sy, d);
        }
        if (lane == 0) {
            int g0;
            if (slot < 40) {
                int c = slot >> 2, dp = slot & 3;
                g0 = 1024 + c * 8 + 2 * dp;
            } else {
                g0 = 1104 + 2 * (slot - 40);
            }
            atomicAdd(&g_scratch[g0], sx);
            atomicAdd(&g_scratch[g0 + 1], sy);
        }
    }

    // ---- last-block finalize ----
    __threadfence();
    __syncthreads();
    __shared__ int sLast;
    if (tid == 0) {
        unsigned prev = atomicAdd(&g_done, 1u);
        sLast = (prev == NBLK - 1u);
    }
    __syncthreads();
    if (!sLast) return;

    __threadfence();   // acquire: all other blocks' scratch writes now visible

    // reuse the sW region as staging
    float* s_sum = sW;          // 1024 floats
    float* dcn   = sW + 1024;   // 80 floats
    volatile float* gs = g_scratch;

    for (int i = tid; i < Bsz * Dd; i += NTHR) s_sum[i] = gs[i];
    if (tid < Cc * Dd) {
        int   c   = tid >> 3;
        float v   = dcg[tid];
        float upd = (gs[1024 + tid] - gs[1104 + c] * v)
                    * (1.0f / (float)(Bsz * Ntot));
        float nv  = v + upd;
        dcn[tid] = nv;
        out[Bsz * Cc + tid] = nv;          // digit_caps_new tail
    }
    __syncthreads();

    // self-clean scratch + counter for the next graph replay
    for (int i = tid; i < 1120; i += NTHR) g_scratch[i] = 0.0f;
    if (tid == 0) g_done = 0u;

    for (int idx = tid; idx < Bsz * Cc; idx += NTHR) {
        int bb = idx / Cc;
        int c  = idx - bb * Cc;
        float s = 0.0f;
        #pragma unroll
        for (int d = 0; d < Dd; d++) s += s_sum[bb * 8 + d] * dcn[c * 8 + d];
        out[idx] = s * (1.0f / (float)Ntot);
    }
}

extern "C" void kernel_launch(void* const* d_in, const int* in_sizes, int n_in,
                              void* d_out, int out_size)
{
    const float* xin = (const float*)d_in[0];  // inputs [128,12,12,32,8]
    const float* Wg  = (const float*)d_in[1];  // W [4608,8,32]
    const float* dcg = (const float*)d_in[2];  // digit_caps [10,8]
    float* out = (float*)d_out;

    size_t smemBytes = (size_t)(JB * WSTR + BB * XSTR + NPAIR * 256) * sizeof(float);
    cudaFuncSetAttribute(caps_main_kernel,
                         cudaFuncAttributeMaxDynamicSharedMemorySize,
                         (int)smemBytes);
    dim3 grid(Jtot / JB, Bsz / BB);
    caps_main_kernel<<<grid, NTHR, smemBytes>>>(xin, Wg, dcg, out);
}